// round 1
// baseline (speedup 1.0000x reference)
#include <cuda_runtime.h>
#include <cuda_bf16.h>

// Problem dims
#define B_   16
#define NC_  31
#define NX_  256
#define NY_  256
#define NO_  3
#define KX_  17
#define KY_  17
#define NG_  (NO_ * NC_)   // 93 (order,channel) groups
#define WIN_ 9             // each group's nonzeros form a 9x9 window

// Compact weights: per (o,c) group a 9x9 tile + window origin (kx0, ky0)
__device__ float g_w[NG_ * WIN_ * WIN_];
__device__ int   g_kx0[NG_];
__device__ int   g_ky0[NG_];

// ---------------------------------------------------------------------------
// Prep: decode locations, find window origin per group, scatter relu(values)
// Single block so __syncthreads orders the phases. Runs every launch
// (deterministic, no caching).
// ---------------------------------------------------------------------------
__global__ void prep_kernel(const float* __restrict__ vk,
                            const int* __restrict__ loc, int nloc) {
    int tid = threadIdx.x;
    for (int i = tid; i < NG_; i += blockDim.x) {
        g_kx0[i] = 1 << 30;
        g_ky0[i] = 1 << 30;
    }
    __syncthreads();
    for (int i = tid; i < nloc; i += blockDim.x) {
        int idx = loc[i];
        int ky = idx % KY_; int t = idx / KY_;
        int kx = t % KX_;   t /= KX_;
        int c  = t % NC_;
        int o  = t / NC_;
        int g = o * NC_ + c;
        atomicMin(&g_kx0[g], kx);
        atomicMin(&g_ky0[g], ky);
    }
    __syncthreads();
    for (int i = tid; i < nloc; i += blockDim.x) {
        int idx = loc[i];
        float v = vk[i];
        v = v > 0.0f ? v : 0.0f;  // ReLU
        int ky = idx % KY_; int t = idx / KY_;
        int kx = t % KX_;   t /= KX_;
        int c  = t % NC_;
        int o  = t / NC_;
        int g = o * NC_ + c;
        g_w[g * (WIN_ * WIN_) + (kx - g_kx0[g]) * WIN_ + (ky - g_ky0[g])] = v;
    }
}

// ---------------------------------------------------------------------------
// Main conv. Each block: one (b, o) pair, a 64-wide x 32-tall output tile.
// Loops over the 31 spectral channels, staging a 40x80 input patch (stride 81
// to break the 8-thread-group bank pattern) in shared memory.
// Thread layout: tx = tid&7 -> 8 col-groups of 8 outputs, ty = tid>>3 -> row.
// Per (c,u): 16 smem loads feed 9x8 = 72 register-blocked FMAs.
// ---------------------------------------------------------------------------
#define TW 64
#define TH 32
#define SW 81          // smem row stride (floats)
#define SH 40          // TH + 8 halo rows
#define SCOLS 80       // TW + 16 halo cols

__global__ __launch_bounds__(256) void conv_kernel(
        const float* __restrict__ x, float* __restrict__ out) {
    __shared__ float tile[SH * SW];
    __shared__ float ws[WIN_ * WIN_];
    __shared__ int s_kx0, s_ky0;

    const int tid = threadIdx.x;
    const int tx = tid & 7;
    const int ty = tid >> 3;

    const int tilec = blockIdx.x & 3;   // 4 col tiles (256/64)
    const int tiler = blockIdx.x >> 2;  // 8 row tiles (256/32)
    const int o = blockIdx.y;
    const int b = blockIdx.z;
    const int i0 = tiler * TH;
    const int j0 = tilec * TW;

    const float* xb = x + (size_t)b * NC_ * NX_ * NY_;

    float acc[8];
#pragma unroll
    for (int jj = 0; jj < 8; ++jj) acc[jj] = 0.0f;

    for (int c = 0; c < NC_; ++c) {
        __syncthreads();  // protect tile/ws from previous iteration's readers

        // stage compact weights + window origin
        if (tid < WIN_ * WIN_) ws[tid] = g_w[(o * NC_ + c) * (WIN_ * WIN_) + tid];
        if (tid == 96) { s_kx0 = g_kx0[o * NC_ + c]; s_ky0 = g_ky0[o * NC_ + c]; }

        // stage input patch rows [i0-4, i0+36), cols [j0-8, j0+72), zero-padded
        const float* xc = xb + (size_t)c * NX_ * NY_;
        for (int idx = tid; idx < SH * SCOLS; idx += 256) {
            int r  = idx / SCOLS;
            int cc = idx - r * SCOLS;
            int gi = i0 + r - 4;
            int gj = j0 + cc - 8;
            float v = 0.0f;
            if ((unsigned)gi < NX_ && (unsigned)gj < NY_)
                v = xc[gi * NY_ + gj];
            tile[r * SW + cc] = v;
        }
        __syncthreads();

        const int kx0 = s_kx0;   // 4 for this dataset
        const int ky0 = s_ky0;   // 0..8 depending on (o,c)
        // smem row for tap u: (i0+ty) + (kx0+u) - 8, rel. to (i0-4)
        const int rowbase = ty + kx0 - 4;
        // smem col for output jj, tap v: j0+tx*8+jj + (ky0+v) - 8, rel. to (j0-8)
        const int colbase = tx * 8 + ky0;

#pragma unroll
        for (int u = 0; u < WIN_; ++u) {
            const float* rowp = &tile[(rowbase + u) * SW + colbase];
            float xr[16];
#pragma unroll
            for (int k = 0; k < 16; ++k) xr[k] = rowp[k];
#pragma unroll
            for (int v = 0; v < WIN_; ++v) {
                const float wv = ws[u * WIN_ + v];
#pragma unroll
                for (int jj = 0; jj < 8; ++jj)
                    acc[jj] = fmaf(xr[v + jj], wv, acc[jj]);
            }
        }
    }

    // write 8 consecutive outputs as two float4 (32B-aligned)
    float* op = out + ((size_t)(b * NO_ + o) * NX_ + (i0 + ty)) * NY_ + j0 + tx * 8;
    float4 v0 = make_float4(acc[0], acc[1], acc[2], acc[3]);
    float4 v1 = make_float4(acc[4], acc[5], acc[6], acc[7]);
    reinterpret_cast<float4*>(op)[0] = v0;
    reinterpret_cast<float4*>(op)[1] = v1;
}

// ---------------------------------------------------------------------------
extern "C" void kernel_launch(void* const* d_in, const int* in_sizes, int n_in,
                              void* d_out, int out_size) {
    const float* x   = (const float*)d_in[0];
    const float* vk  = (const float*)d_in[1];
    const int*   loc = (const int*)d_in[2];
    float* out = (float*)d_out;

    int nloc = in_sizes[2];
    int batch = in_sizes[0] / (NC_ * NX_ * NY_);

    prep_kernel<<<1, 256>>>(vk, loc, nloc);

    dim3 grid((NX_ / TH) * (NY_ / TW), NO_, batch);  // (32, 3, 16)
    conv_kernel<<<grid, 256>>>(x, out);
}